// round 13
// baseline (speedup 1.0000x reference)
#include <cuda_runtime.h>
#include <cuda_fp16.h>
#include <cstdint>

// ---------------------------------------------------------------------------
// ProbSparseAttention  B=2, L=4096, dm=128, H=8, D=16, sample_k=41
// Score passes + QKV GEMM: split-fp16 (hi+lo) mma.sync, chained accumulator.
// Top-k: radix select w/ warp-shuffle scan. Output GEMM exact fp32.
// ---------------------------------------------------------------------------

#define L      4096
#define DM     128
#define H      8
#define DH     16
#define NBH    16
#define SK     41
#define LOG2E  1.4426950408889634f
#define C1     (0.25f * LOG2E)
#define CHK    128
#define NCH    (L / CHK)

// Scratch (device globals; no allocation allowed)
__device__ float  g_Q[NBH * L * DH];
__device__ float  g_K[NBH * L * DH];
__device__ float  g_V[NBH * L * DH];
__device__ __half g_Qh[NBH * L * DH];
__device__ __half g_Ql[NBH * L * DH];
__device__ __half g_Kh[NBH * L * DH];
__device__ __half g_Kl[NBH * L * DH];
__device__ __half g_WTh[3 * DM * DM];   // W^T split (q,k,v): [mat][n][k]
__device__ __half g_WTl[3 * DM * DM];
__device__ float  g_ml[NBH * L];
__device__ float  g_mean[NBH * L];
__device__ int    g_idx[NBH * SK];
__device__ float  g_ctx[2 * L * DM];

__device__ __forceinline__ float ex2f(float x) {
    float r;
    asm("ex2.approx.ftz.f32 %0, %1;" : "=f"(r) : "f"(x));
    return r;
}
__device__ __forceinline__ uint32_t smem_u32(const void* p) {
    return (uint32_t)__cvta_generic_to_shared(p);
}
__device__ __forceinline__ void cpasync16(uint32_t saddr, const void* gptr) {
    asm volatile("cp.async.ca.shared.global [%0], [%1], 16;" :: "r"(saddr), "l"(gptr));
}
__device__ __forceinline__ void cp_commit() { asm volatile("cp.async.commit_group;"); }
template <int N>
__device__ __forceinline__ void cp_wait() { asm volatile("cp.async.wait_group %0;" :: "n"(N)); }

__device__ __forceinline__ void ldsm4(uint32_t r[4], uint32_t addr) {
    asm volatile("ldmatrix.sync.aligned.m8n8.x4.shared.b16 {%0,%1,%2,%3}, [%4];"
                 : "=r"(r[0]), "=r"(r[1]), "=r"(r[2]), "=r"(r[3]) : "r"(addr));
}
__device__ __forceinline__ void mma_z(float c[4], const uint32_t a[4],
                                      uint32_t b0, uint32_t b1) {
    asm volatile(
        "mma.sync.aligned.m16n8k16.row.col.f32.f16.f16.f32 "
        "{%0,%1,%2,%3}, {%4,%5,%6,%7}, {%8,%9}, {%10,%11,%12,%13};"
        : "=f"(c[0]), "=f"(c[1]), "=f"(c[2]), "=f"(c[3])
        : "r"(a[0]), "r"(a[1]), "r"(a[2]), "r"(a[3]), "r"(b0), "r"(b1),
          "f"(0.0f), "f"(0.0f), "f"(0.0f), "f"(0.0f));
}
__device__ __forceinline__ void mma_acc(float c[4], const uint32_t a[4],
                                        uint32_t b0, uint32_t b1) {
    asm volatile(
        "mma.sync.aligned.m16n8k16.row.col.f32.f16.f16.f32 "
        "{%0,%1,%2,%3}, {%4,%5,%6,%7}, {%8,%9}, {%0,%1,%2,%3};"
        : "+f"(c[0]), "+f"(c[1]), "+f"(c[2]), "+f"(c[3])
        : "r"(a[0]), "r"(a[1]), "r"(a[2]), "r"(a[3]), "r"(b0), "r"(b1));
}

// Split two consecutive fp32 into packed hi/lo fp16 pairs.
__device__ __forceinline__ void split2(const float* p, uint32_t& hi, uint32_t& lo) {
    float2 f = *(const float2*)p;
    __half2 h = __floats2half2_rn(f.x, f.y);
    float2 fr = __half22float2(h);
    __half2 l = __floats2half2_rn(f.x - fr.x, f.y - fr.y);
    hi = *(uint32_t*)&h;
    lo = *(uint32_t*)&l;
}

__device__ __forceinline__ float dot16(const float4 a0, const float4 a1,
                                       const float4 a2, const float4 a3,
                                       const float4 b0, const float4 b1,
                                       const float4 b2, const float4 b3) {
    float s0 = a0.x * b0.x; s0 = fmaf(a0.y, b0.y, s0); s0 = fmaf(a0.z, b0.z, s0); s0 = fmaf(a0.w, b0.w, s0);
    float s1 = a1.x * b1.x; s1 = fmaf(a1.y, b1.y, s1); s1 = fmaf(a1.z, b1.z, s1); s1 = fmaf(a1.w, b1.w, s1);
    float s2 = a2.x * b2.x; s2 = fmaf(a2.y, b2.y, s2); s2 = fmaf(a2.z, b2.z, s2); s2 = fmaf(a2.w, b2.w, s2);
    float s3 = a3.x * b3.x; s3 = fmaf(a3.y, b3.y, s3); s3 = fmaf(a3.z, b3.z, s3); s3 = fmaf(a3.w, b3.w, s3);
    return (s0 + s1) + (s2 + s3);
}

// ---------------------------------------------------------------------------
// Prep: transpose + split Wq/Wk/Wv into W^T hi/lo [n][k].
// ---------------------------------------------------------------------------
__global__ void __launch_bounds__(256)
prep_w_kernel(const float* __restrict__ Wq, const float* __restrict__ Wk,
              const float* __restrict__ Wv) {
    int mat = blockIdx.y;
    const float* W = (mat == 0) ? Wq : (mat == 1) ? Wk : Wv;
    int idx = blockIdx.x * 256 + threadIdx.x;   // 16384 per mat
    int n  = idx & 127;
    int kk = idx >> 7;
    float v = W[kk * DM + n];                   // coalesced in n
    __half hi = __float2half_rn(v);
    g_WTh[mat * DM * DM + n * DM + kk] = hi;
    g_WTl[mat * DM * DM + n * DM + kk] = __float2half_rn(v - __half2float(hi));
}

// ---------------------------------------------------------------------------
// QKV GEMM (split-fp16 MMA): C = x @ W + bias, head-major + hi/lo emit.
// x tile staged fp32 in smem; A-frags converted in-register; B-frags from
// prepped W^T hi/lo in global (L1-resident, shared by all blocks).
// Block: 64 rows x 128 cols, 8 warps: warp(wr,wc) -> rows 16*wr, cols 64*wc.
// ---------------------------------------------------------------------------
__global__ void __launch_bounds__(256)
qkv_gemm_tc_kernel(const float* __restrict__ x,
                   const float* __restrict__ bq, const float* __restrict__ bk,
                   const float* __restrict__ bv) {
    __shared__ float sX[64][136];   // pad 136: conflict-light LDS.64 frag reads

    const int which = blockIdx.y;
    const float* bias = (which == 0) ? bq : (which == 1) ? bk : bv;
    float* out  = (which == 0) ? g_Q : (which == 1) ? g_K : g_V;
    __half* ohi = (which == 0) ? g_Qh : (which == 1) ? g_Kh : (__half*)0;
    __half* olo = (which == 0) ? g_Ql : (which == 1) ? g_Kl : (__half*)0;
    const __half* WTh = g_WTh + which * DM * DM;
    const __half* WTl = g_WTl + which * DM * DM;

    const int tid = threadIdx.x;
    const int warp = tid >> 5, lane = tid & 31;
    const int g = lane >> 2, tg = lane & 3;
    const int wr = warp & 3, wc = warp >> 2;
    const int rowBase = blockIdx.x * 64;

    // Stage x tile: 64 x 128 fp32
#pragma unroll
    for (int i = tid; i < 2048; i += 256) {
        int r  = i >> 5;
        int c4 = i & 31;
        float4 v = *(const float4*)(x + (size_t)(rowBase + r) * DM + c4 * 4);
        sX[r][c4 * 4 + 0] = v.x;
        sX[r][c4 * 4 + 1] = v.y;
        sX[r][c4 * 4 + 2] = v.z;
        sX[r][c4 * 4 + 3] = v.w;
    }
    __syncthreads();

    const int r0 = wr * 16 + g;
    const int r1 = r0 + 8;
    const int n0 = wc * 64;

    float acc[8][4];
#pragma unroll
    for (int s = 0; s < 8; s++)
#pragma unroll
        for (int c = 0; c < 4; c++) acc[s][c] = 0.0f;

#pragma unroll
    for (int ks = 0; ks < 8; ks++) {
        const int k = ks * 16;
        uint32_t ah[4], al[4];
        split2(&sX[r0][k + tg * 2],     ah[0], al[0]);
        split2(&sX[r1][k + tg * 2],     ah[1], al[1]);
        split2(&sX[r0][k + 8 + tg * 2], ah[2], al[2]);
        split2(&sX[r1][k + 8 + tg * 2], ah[3], al[3]);

#pragma unroll
        for (int sub = 0; sub < 8; sub++) {
            const int n = n0 + sub * 8;
            uint32_t bh0 = *(const uint32_t*)(WTh + (size_t)(n + g) * DM + k + tg * 2);
            uint32_t bh1 = *(const uint32_t*)(WTh + (size_t)(n + g) * DM + k + 8 + tg * 2);
            uint32_t bl0 = *(const uint32_t*)(WTl + (size_t)(n + g) * DM + k + tg * 2);
            uint32_t bl1 = *(const uint32_t*)(WTl + (size_t)(n + g) * DM + k + 8 + tg * 2);
            mma_acc(acc[sub], ah, bh0, bh1);
            mma_acc(acc[sub], ah, bl0, bl1);
            mma_acc(acc[sub], al, bh0, bh1);
        }
    }

#pragma unroll
    for (int sub = 0; sub < 8; sub++) {
        const int n = n0 + sub * 8;
#pragma unroll
        for (int c = 0; c < 4; c++) {
            int row = rowBase + ((c >= 2) ? r1 : r0);
            int col = n + tg * 2 + (c & 1);
            float val = acc[sub][c] + bias[col];
            int b = row >> 12;
            int l = row & (L - 1);
            int h = col >> 4;
            int d = col & 15;
            size_t o = ((size_t)(b * H + h) * L + l) * DH + d;
            out[o] = val;
            if (ohi) {
                __half hi = __float2half_rn(val);
                ohi[o] = hi;
                olo[o] = __float2half_rn(val - __half2float(hi));
            }
        }
    }
}

// ---------------------------------------------------------------------------
// Output GEMM (fp32, smem-tiled): out = ctx @ Wo + bo
// ---------------------------------------------------------------------------
__global__ void __launch_bounds__(256)
out_gemm_kernel(const float* __restrict__ Wo, const float* __restrict__ bo,
                float* __restrict__ outp) {
    __shared__ float sA[64][33];
    __shared__ float sW[32][128];

    const int tid = threadIdx.x;
    const int tx = tid & 15;
    const int ty = tid >> 4;
    const int rowBase = blockIdx.x * 64;
    const float* A = g_ctx;

    float acc[4][8];
#pragma unroll
    for (int r = 0; r < 4; r++)
#pragma unroll
        for (int c = 0; c < 8; c++) acc[r][c] = 0.0f;

    for (int kc = 0; kc < 128; kc += 32) {
#pragma unroll
        for (int i = tid; i < 512; i += 256) {
            int r  = i >> 3;
            int c4 = i & 7;
            float4 v = *(const float4*)(A + (size_t)(rowBase + r) * DM + kc + c4 * 4);
            sA[r][c4 * 4 + 0] = v.x;
            sA[r][c4 * 4 + 1] = v.y;
            sA[r][c4 * 4 + 2] = v.z;
            sA[r][c4 * 4 + 3] = v.w;
        }
#pragma unroll
        for (int i = tid; i < 1024; i += 256) {
            int r  = i >> 5;
            int c4 = i & 31;
            *(float4*)(&sW[r][c4 * 4]) = *(const float4*)(Wo + (size_t)(kc + r) * DM + c4 * 4);
        }
        __syncthreads();

#pragma unroll
        for (int k = 0; k < 32; k++) {
            float a[4], b[8];
#pragma unroll
            for (int r = 0; r < 4; r++) a[r] = sA[ty * 4 + r][k];
#pragma unroll
            for (int c = 0; c < 8; c++) b[c] = sW[k][tx + 16 * c];
#pragma unroll
            for (int r = 0; r < 4; r++)
#pragma unroll
                for (int c = 0; c < 8; c++) acc[r][c] = fmaf(a[r], b[c], acc[r][c]);
        }
        __syncthreads();
    }

#pragma unroll
    for (int r = 0; r < 4; r++) {
        int row = rowBase + ty * 4 + r;
#pragma unroll
        for (int c = 0; c < 8; c++) {
            int col = tx + 16 * c;
            outp[(size_t)row * DM + col] = acc[r][c] + bo[col];
        }
    }
}

// ---------------------------------------------------------------------------
// Pass A (split MMA, chained acc, double-buffered): g_ml[q] = max_k(q.k)*C1
// ---------------------------------------------------------------------------
__global__ void __launch_bounds__(256) rowmax_mma_kernel() {
    __shared__ __align__(16) __half sKh[2][CHK * 24];
    __shared__ __align__(16) __half sKl[2][CHK * 24];

    const int bh = blockIdx.y, tid = threadIdx.x;
    const int warp = tid >> 5, lane = tid & 31;
    const int g = lane >> 2, tg = lane & 3;
    const __half* Qhp = g_Qh + (size_t)bh * L * DH;
    const __half* Qlp = g_Ql + (size_t)bh * L * DH;
    const __half* Khp = g_Kh + (size_t)bh * L * DH;
    const __half* Klp = g_Kl + (size_t)bh * L * DH;

    const int q0 = blockIdx.x * 128 + warp * 16 + g;

    uint32_t ah[4], al[4];
    ah[0] = *(const uint32_t*)(Qhp + (size_t)q0 * 16 + tg * 2);
    ah[1] = *(const uint32_t*)(Qhp + (size_t)(q0 + 8) * 16 + tg * 2);
    ah[2] = *(const uint32_t*)(Qhp + (size_t)q0 * 16 + tg * 2 + 8);
    ah[3] = *(const uint32_t*)(Qhp + (size_t)(q0 + 8) * 16 + tg * 2 + 8);
    al[0] = *(const uint32_t*)(Qlp + (size_t)q0 * 16 + tg * 2);
    al[1] = *(const uint32_t*)(Qlp + (size_t)(q0 + 8) * 16 + tg * 2);
    al[2] = *(const uint32_t*)(Qlp + (size_t)q0 * 16 + tg * 2 + 8);
    al[3] = *(const uint32_t*)(Qlp + (size_t)(q0 + 8) * 16 + tg * 2 + 8);

    float mx0 = -1e30f, mx1 = -1e30f;

    const int lrow = (lane & 7) + ((lane >> 4) << 3);
    const int lcol = (lane & 8);

    auto load_chunk = [&](int buf, int ch) {
        int row = tid >> 1, h8 = (tid & 1) * 8;
        cpasync16(smem_u32(&sKh[buf][row * 24 + h8]),
                  Khp + (size_t)(ch * CHK + row) * 16 + h8);
        cpasync16(smem_u32(&sKl[buf][row * 24 + h8]),
                  Klp + (size_t)(ch * CHK + row) * 16 + h8);
    };

    load_chunk(0, 0);
    cp_commit();

    for (int ch = 0; ch < NCH; ch++) {
        int buf = ch & 1;
        if (ch + 1 < NCH) { load_chunk(buf ^ 1, ch + 1); cp_commit(); cp_wait<1>(); }
        else              { cp_wait<0>(); }
        __syncthreads();

        uint32_t baseh = smem_u32(&sKh[buf][lrow * 24 + lcol]);
        uint32_t basel = smem_u32(&sKl[buf][lrow * 24 + lcol]);
#pragma unroll
        for (int kb = 0; kb < CHK; kb += 16) {
            uint32_t rh[4], rl[4];
            ldsm4(rh, baseh + kb * 48);
            ldsm4(rl, basel + kb * 48);

            float c0[4], c1[4];
            mma_z(c0, ah, rh[0], rh[1]);
            mma_acc(c0, ah, rl[0], rl[1]);
            mma_acc(c0, al, rh[0], rh[1]);
            mma_z(c1, ah, rh[2], rh[3]);
            mma_acc(c1, ah, rl[2], rl[3]);
            mma_acc(c1, al, rh[2], rh[3]);

            mx0 = fmaxf(mx0, fmaxf(fmaxf(c0[0], c0[1]), fmaxf(c1[0], c1[1])));
            mx1 = fmaxf(mx1, fmaxf(fmaxf(c0[2], c0[3]), fmaxf(c1[2], c1[3])));
        }
        __syncthreads();
    }

    mx0 = fmaxf(mx0, __shfl_xor_sync(0xffffffffu, mx0, 1));
    mx0 = fmaxf(mx0, __shfl_xor_sync(0xffffffffu, mx0, 2));
    mx1 = fmaxf(mx1, __shfl_xor_sync(0xffffffffu, mx1, 1));
    mx1 = fmaxf(mx1, __shfl_xor_sync(0xffffffffu, mx1, 2));
    if (tg == 0) {
        g_ml[bh * L + q0]     = mx0 * C1;
        g_ml[bh * L + q0 + 8] = mx1 * C1;
    }
}

// ---------------------------------------------------------------------------
// Pass B (split MMA, chained acc): warp owns 16 keys, loops queries.
// ---------------------------------------------------------------------------
__global__ void __launch_bounds__(256) keysum_mma_kernel() {
    __shared__ __align__(16) __half sQh[2][CHK * 24];
    __shared__ __align__(16) __half sQl[2][CHK * 24];
    __shared__ __align__(16) float  sM[2][CHK];

    const int bh = blockIdx.y, tid = threadIdx.x;
    const int warp = tid >> 5, lane = tid & 31;
    const int g = lane >> 2, tg = lane & 3;
    const __half* Qhp = g_Qh + (size_t)bh * L * DH;
    const __half* Qlp = g_Ql + (size_t)bh * L * DH;
    const __half* Khp = g_Kh + (size_t)bh * L * DH;
    const __half* Klp = g_Kl + (size_t)bh * L * DH;
    const float*  Mlp = g_ml + (size_t)bh * L;

    const int kbase = blockIdx.x * 128 + warp * 16;

    uint32_t kh0a = *(const uint32_t*)(Khp + (size_t)(kbase + g) * 16 + tg * 2);
    uint32_t kh1a = *(const uint32_t*)(Khp + (size_t)(kbase + g) * 16 + tg * 2 + 8);
    uint32_t kl0a = *(const uint32_t*)(Klp + (size_t)(kbase + g) * 16 + tg * 2);
    uint32_t kl1a = *(const uint32_t*)(Klp + (size_t)(kbase + g) * 16 + tg * 2 + 8);
    uint32_t kh0b = *(const uint32_t*)(Khp + (size_t)(kbase + 8 + g) * 16 + tg * 2);
    uint32_t kh1b = *(const uint32_t*)(Khp + (size_t)(kbase + 8 + g) * 16 + tg * 2 + 8);
    uint32_t kl0b = *(const uint32_t*)(Klp + (size_t)(kbase + 8 + g) * 16 + tg * 2);
    uint32_t kl1b = *(const uint32_t*)(Klp + (size_t)(kbase + 8 + g) * 16 + tg * 2 + 8);

    float acc_a0 = 0.0f, acc_a1 = 0.0f, acc_b0 = 0.0f, acc_b1 = 0.0f;

    const int mi = lane >> 3;
    const int lrow = (lane & 7) + ((mi & 1) << 3);
    const int lcol = (mi >> 1) << 3;

    auto load_chunk = [&](int buf, int ch) {
        int row = tid >> 1, h8 = (tid & 1) * 8;
        cpasync16(smem_u32(&sQh[buf][row * 24 + h8]),
                  Qhp + (size_t)(ch * CHK + row) * 16 + h8);
        cpasync16(smem_u32(&sQl[buf][row * 24 + h8]),
                  Qlp + (size_t)(ch * CHK + row) * 16 + h8);
        if (tid < CHK / 4)
            cpasync16(smem_u32(&sM[buf][tid * 4]), Mlp + ch * CHK + tid * 4);
    };

    load_chunk(0, 0);
    cp_commit();

    for (int ch = 0; ch < NCH; ch++) {
        int buf = ch & 1;
        if (ch + 1 < NCH) { load_chunk(buf ^ 1, ch + 1); cp_commit(); cp_wait<1>(); }
        else              { cp_wait<0>(); }
        __syncthreads();

        uint32_t baseh = smem_u32(&sQh[buf][lrow * 24 + lcol]);
        uint32_t basel = smem_u32(&sQl[buf][lrow * 24 + lcol]);
#pragma unroll
        for (int qb = 0; qb < CHK; qb += 16) {
            uint32_t qah[4], qal[4];
            ldsm4(qah, baseh + qb * 48);
            ldsm4(qal, basel + qb * 48);
            float ml0 = sM[buf][qb + g], ml1 = sM[buf][qb + g + 8];

            float ca[4], cb[4];
            mma_z(ca, qah, kh0a, kh1a);
            mma_acc(ca, qah, kl0a, kl1a);
            mma_acc(ca, qal, kh0a, kh1a);
            mma_z(cb, qah, kh0b, kh1b);
            mma_acc(cb, qah, kl0b, kl1b);
            mma_acc(cb, qal, kh0b, kh1b);

            acc_a0 += ex2f(fmaf(ca[0], C1, -ml0)) + ex2f(fmaf(ca[2], C1, -ml1));
            acc_a1 += ex2f(fmaf(ca[1], C1, -ml0)) + ex2f(fmaf(ca[3], C1, -ml1));
            acc_b0 += ex2f(fmaf(cb[0], C1, -ml0)) + ex2f(fmaf(cb[2], C1, -ml1));
            acc_b1 += ex2f(fmaf(cb[1], C1, -ml0)) + ex2f(fmaf(cb[3], C1, -ml1));
        }
        __syncthreads();
    }

#pragma unroll
    for (int s = 4; s <= 16; s <<= 1) {
        acc_a0 += __shfl_xor_sync(0xffffffffu, acc_a0, s);
        acc_a1 += __shfl_xor_sync(0xffffffffu, acc_a1, s);
        acc_b0 += __shfl_xor_sync(0xffffffffu, acc_b0, s);
        acc_b1 += __shfl_xor_sync(0xffffffffu, acc_b1, s);
    }
    if (g == 0) {
        g_mean[bh * L + kbase + tg * 2]         = acc_a0;
        g_mean[bh * L + kbase + tg * 2 + 1]     = acc_a1;
        g_mean[bh * L + kbase + 8 + tg * 2]     = acc_b0;
        g_mean[bh * L + kbase + 8 + tg * 2 + 1] = acc_b1;
    }
}

// ---------------------------------------------------------------------------
// Top-41 per (b,h): radix select with warp-shuffle suffix scan.
// ---------------------------------------------------------------------------
__global__ void __launch_bounds__(256) topk_kernel() {
    __shared__ int hist[256];
    __shared__ int sfx[256];
    __shared__ int wsum[8];
    __shared__ uint32_t s_prefix;
    __shared__ int s_need;
    __shared__ int s_cnt, s_eqc;
    __shared__ int eq_idx[64];

    const int bh = blockIdx.x, tid = threadIdx.x;
    const int lane = tid & 31, w = tid >> 5;

    uint32_t u[16];
#pragma unroll
    for (int j = 0; j < 16; j++) {
        uint32_t b = __float_as_uint(g_mean[bh * L + (j << 8) + tid]);
        u[j] = (b & 0x80000000u) ? ~b : (b | 0x80000000u);
    }

    uint32_t prefix = 0;
    int need = SK;
#pragma unroll
    for (int pass = 0; pass < 4; pass++) {
        int sh = 24 - pass * 8;
        hist[tid] = 0;
        __syncthreads();
#pragma unroll
        for (int j = 0; j < 16; j++) {
            bool act = (pass == 0) || ((u[j] >> (sh + 8)) == prefix);
            if (act) atomicAdd(&hist[(u[j] >> sh) & 255], 1);
        }
        __syncthreads();

        // warp-level suffix scan over 256 bins
        int v = hist[tid];
#pragma unroll
        for (int off = 1; off < 32; off <<= 1) {
            int t = __shfl_down_sync(0xffffffffu, v, off);
            if (lane + off < 32) v += t;
        }
        if (lane == 0) wsum[w] = v;   // warp total
        __syncthreads();
        int add = 0;
#pragma unroll
        for (int ww = 0; ww < 8; ww++)
            if (ww > w) add += wsum[ww];
        v += add;
        sfx[tid] = v;
        __syncthreads();

        int nxt = (tid < 255) ? sfx[tid + 1] : 0;
        if (sfx[tid] >= need && nxt < need) {
            s_prefix = (prefix << 8) | (uint32_t)tid;
            s_need = need - nxt;
        }
        __syncthreads();
        prefix = s_prefix;
        need = s_need;
        __syncthreads();
    }

    const uint32_t T = prefix;
    if (tid == 0) { s_cnt = 0; s_eqc = 0; }
    __syncthreads();
#pragma unroll
    for (int j = 0; j < 16; j++) {
        if (u[j] > T) {
            int p = atomicAdd(&s_cnt, 1);
            g_idx[bh * SK + p] = (j << 8) + tid;
        } else if (u[j] == T) {
            int p = atomicAdd(&s_eqc, 1);
            if (p < 64) eq_idx[p] = (j << 8) + tid;
        }
    }
    __syncthreads();
    if (tid == 0) {
        int base = s_cnt;
        int m = s_eqc < 64 ? s_eqc : 64;
        for (int i = 1; i < m; i++) {
            int key = eq_idx[i], k2 = i - 1;
            while (k2 >= 0 && eq_idx[k2] > key) { eq_idx[k2 + 1] = eq_idx[k2]; k2--; }
            eq_idx[k2 + 1] = key;
        }
        for (int r = 0; r < need && r < m; r++)
            g_idx[bh * SK + base + r] = eq_idx[r];
    }
}

// ---------------------------------------------------------------------------
// Sparse attention: softmax(Q . Ks^T * 0.25) @ Vs, 41 sampled keys (exact fp32)
// ---------------------------------------------------------------------------
__global__ void __launch_bounds__(256) sparse_attn_kernel() {
    __shared__ float sKs[SK * DH];
    __shared__ float sVs[SK * DH];

    const int bh = blockIdx.y, tid = threadIdx.x;
    const float* Qb = g_Q + (size_t)bh * L * DH;
    const float* Kb = g_K + (size_t)bh * L * DH;
    const float* Vb = g_V + (size_t)bh * L * DH;

    for (int i = tid; i < SK * DH; i += 256) {
        int s = i >> 4, d = i & 15;
        int kk = g_idx[bh * SK + s];
        sKs[i] = Kb[(size_t)kk * DH + d];
        sVs[i] = Vb[(size_t)kk * DH + d];
    }
    __syncthreads();

    const int q = blockIdx.x * 256 + tid;
    const float4* qp = (const float4*)(Qb + (size_t)q * DH);
    float4 a0 = qp[0], a1 = qp[1], a2 = qp[2], a3 = qp[3];

    float sc[SK];
    float mx = -1e30f;
#pragma unroll
    for (int s = 0; s < SK; s++) {
        const float4* kp = (const float4*)(sKs + s * DH);
        float d = dot16(a0, a1, a2, a3, kp[0], kp[1], kp[2], kp[3]);
        sc[s] = d;
        mx = fmaxf(mx, d);
    }

    float sum = 0.0f;
    float4 o0 = {0, 0, 0, 0}, o1 = {0, 0, 0, 0}, o2 = {0, 0, 0, 0}, o3 = {0, 0, 0, 0};
#pragma unroll
    for (int s = 0; s < SK; s++) {
        float w = ex2f((sc[s] - mx) * C1);
        sum += w;
        const float4* vp = (const float4*)(sVs + s * DH);
        float4 v0 = vp[0], v1 = vp[1], v2 = vp[2], v3 = vp[3];
        o0.x = fmaf(w, v0.x, o0.x); o0.y = fmaf(w, v0.y, o0.y);
        o0.z = fmaf(w, v0.z, o0.z); o0.w = fmaf(w, v0.w, o0.w);
        o1.x = fmaf(w, v1.x, o1.x); o1.y = fmaf(w, v1.y, o1.y);
        o1.z = fmaf(w, v1.z, o1.z); o1.w = fmaf(w, v1.w, o1.w);
        o2.x = fmaf(w, v2.x, o2.x); o2.y = fmaf(w, v2.y, o2.y);
        o2.z = fmaf(w, v2.z, o2.z); o2.w = fmaf(w, v2.w, o2.w);
        o3.x = fmaf(w, v3.x, o3.x); o3.y = fmaf(w, v3.y, o3.y);
        o3.z = fmaf(w, v3.z, o3.z); o3.w = fmaf(w, v3.w, o3.w);
    }
    float inv = 1.0f / sum;

    const int b = bh >> 3;
    const int h = bh & 7;
    float* op = g_ctx + ((size_t)b * L + q) * DM + h * DH;
    *(float4*)(op + 0)  = make_float4(o0.x * inv, o0.y * inv, o0.z * inv, o0.w * inv);
    *(float4*)(op + 4)  = make_float4(o1.x * inv, o1.y * inv, o1.z * inv, o1.w * inv);
    *(float4*)(op + 8)  = make_float4(o2.x * inv, o2.y * inv, o2.z * inv, o2.w * inv);
    *(float4*)(op + 12) = make_float4(o3.x * inv, o3.y * inv, o3.z * inv, o3.w * inv);
}

// ---------------------------------------------------------------------------
extern "C" void kernel_launch(void* const* d_in, const int* in_sizes, int n_in,
                              void* d_out, int out_size) {
    const float* x  = (const float*)d_in[0];
    const float* Wq = (const float*)d_in[1];
    const float* bq = (const float*)d_in[2];
    const float* Wk = (const float*)d_in[3];
    const float* bk = (const float*)d_in[4];
    const float* Wv = (const float*)d_in[5];
    const float* bv = (const float*)d_in[6];
    const float* Wo = (const float*)d_in[7];
    const float* bo = (const float*)d_in[8];

    prep_w_kernel<<<dim3(64, 3), 256>>>(Wq, Wk, Wv);
    qkv_gemm_tc_kernel<<<dim3(128, 3), 256>>>(x, bq, bk, bv);
    rowmax_mma_kernel<<<dim3(32, NBH), 256>>>();
    keysum_mma_kernel<<<dim3(32, NBH), 256>>>();
    topk_kernel<<<NBH, 256>>>();
    sparse_attn_kernel<<<dim3(16, NBH), 256>>>();
    out_gemm_kernel<<<128, 256>>>(Wo, bo, (float*)d_out);
}

// round 15
// speedup vs baseline: 1.1029x; 1.1029x over previous
#include <cuda_runtime.h>
#include <cuda_fp16.h>
#include <cstdint>

// ---------------------------------------------------------------------------
// ProbSparseAttention  B=2, L=4096, dm=128, H=8, D=16, sample_k=41
// Score passes: split-fp16 (hi+lo) mma.sync, chained accumulator, cp.async
// double-buffered, 128-thread blocks for occupancy. Top-k: radix select.
// GEMMs + output path exact fp32.
// ---------------------------------------------------------------------------

#define L      4096
#define DM     128
#define H      8
#define DH     16
#define NBH    16
#define SK     41
#define LOG2E  1.4426950408889634f
#define C1     (0.25f * LOG2E)
#define CHK    128
#define NCH    (L / CHK)

// Scratch (device globals; no allocation allowed)
__device__ float  g_Q[NBH * L * DH];
__device__ float  g_K[NBH * L * DH];
__device__ float  g_V[NBH * L * DH];
__device__ __half g_Qh[NBH * L * DH];
__device__ __half g_Ql[NBH * L * DH];
__device__ __half g_Kh[NBH * L * DH];
__device__ __half g_Kl[NBH * L * DH];
__device__ float  g_ml[NBH * L];
__device__ float  g_mean[NBH * L];
__device__ int    g_idx[NBH * SK];
__device__ float  g_ctx[2 * L * DM];

__device__ __forceinline__ float ex2f(float x) {
    float r;
    asm("ex2.approx.ftz.f32 %0, %1;" : "=f"(r) : "f"(x));
    return r;
}
__device__ __forceinline__ uint32_t smem_u32(const void* p) {
    return (uint32_t)__cvta_generic_to_shared(p);
}
__device__ __forceinline__ void cpasync16(uint32_t saddr, const void* gptr) {
    asm volatile("cp.async.ca.shared.global [%0], [%1], 16;" :: "r"(saddr), "l"(gptr));
}
__device__ __forceinline__ void cp_commit() { asm volatile("cp.async.commit_group;"); }
template <int N>
__device__ __forceinline__ void cp_wait() { asm volatile("cp.async.wait_group %0;" :: "n"(N)); }

__device__ __forceinline__ void ldsm4(uint32_t r[4], uint32_t addr) {
    asm volatile("ldmatrix.sync.aligned.m8n8.x4.shared.b16 {%0,%1,%2,%3}, [%4];"
                 : "=r"(r[0]), "=r"(r[1]), "=r"(r[2]), "=r"(r[3]) : "r"(addr));
}
__device__ __forceinline__ void mma_z(float c[4], const uint32_t a[4],
                                      uint32_t b0, uint32_t b1) {
    asm volatile(
        "mma.sync.aligned.m16n8k16.row.col.f32.f16.f16.f32 "
        "{%0,%1,%2,%3}, {%4,%5,%6,%7}, {%8,%9}, {%10,%11,%12,%13};"
        : "=f"(c[0]), "=f"(c[1]), "=f"(c[2]), "=f"(c[3])
        : "r"(a[0]), "r"(a[1]), "r"(a[2]), "r"(a[3]), "r"(b0), "r"(b1),
          "f"(0.0f), "f"(0.0f), "f"(0.0f), "f"(0.0f));
}
__device__ __forceinline__ void mma_acc(float c[4], const uint32_t a[4],
                                        uint32_t b0, uint32_t b1) {
    asm volatile(
        "mma.sync.aligned.m16n8k16.row.col.f32.f16.f16.f32 "
        "{%0,%1,%2,%3}, {%4,%5,%6,%7}, {%8,%9}, {%0,%1,%2,%3};"
        : "+f"(c[0]), "+f"(c[1]), "+f"(c[2]), "+f"(c[3])
        : "r"(a[0]), "r"(a[1]), "r"(a[2]), "r"(a[3]), "r"(b0), "r"(b1));
}

__device__ __forceinline__ float dot16(const float4 a0, const float4 a1,
                                       const float4 a2, const float4 a3,
                                       const float4 b0, const float4 b1,
                                       const float4 b2, const float4 b3) {
    float s0 = a0.x * b0.x; s0 = fmaf(a0.y, b0.y, s0); s0 = fmaf(a0.z, b0.z, s0); s0 = fmaf(a0.w, b0.w, s0);
    float s1 = a1.x * b1.x; s1 = fmaf(a1.y, b1.y, s1); s1 = fmaf(a1.z, b1.z, s1); s1 = fmaf(a1.w, b1.w, s1);
    float s2 = a2.x * b2.x; s2 = fmaf(a2.y, b2.y, s2); s2 = fmaf(a2.z, b2.z, s2); s2 = fmaf(a2.w, b2.w, s2);
    float s3 = a3.x * b3.x; s3 = fmaf(a3.y, b3.y, s3); s3 = fmaf(a3.z, b3.z, s3); s3 = fmaf(a3.w, b3.w, s3);
    return (s0 + s1) + (s2 + s3);
}

// ---------------------------------------------------------------------------
// GEMM: C[8192,128] = A[8192,128] @ W[128,128] + bias (fp32, smem-tiled).
// HEADMAJOR also emits split-fp16 (hi, lo) copies for the score passes.
// ---------------------------------------------------------------------------
template <bool HEADMAJOR>
__device__ __forceinline__ void gemm_body(const float* __restrict__ A,
                                          const float* __restrict__ W,
                                          const float* __restrict__ bias,
                                          float* __restrict__ C,
                                          __half* __restrict__ Chi,
                                          __half* __restrict__ Clo) {
    __shared__ float sA[64][33];
    __shared__ float sW[32][128];

    const int tid = threadIdx.x;
    const int tx = tid & 15;
    const int ty = tid >> 4;
    const int rowBase = blockIdx.x * 64;

    float acc[4][8];
#pragma unroll
    for (int r = 0; r < 4; r++)
#pragma unroll
        for (int c = 0; c < 8; c++) acc[r][c] = 0.0f;

    for (int kc = 0; kc < 128; kc += 32) {
#pragma unroll
        for (int i = tid; i < 512; i += 256) {
            int r  = i >> 3;
            int c4 = i & 7;
            float4 v = *(const float4*)(A + (size_t)(rowBase + r) * DM + kc + c4 * 4);
            sA[r][c4 * 4 + 0] = v.x;
            sA[r][c4 * 4 + 1] = v.y;
            sA[r][c4 * 4 + 2] = v.z;
            sA[r][c4 * 4 + 3] = v.w;
        }
#pragma unroll
        for (int i = tid; i < 1024; i += 256) {
            int r  = i >> 5;
            int c4 = i & 31;
            *(float4*)(&sW[r][c4 * 4]) = *(const float4*)(W + (size_t)(kc + r) * DM + c4 * 4);
        }
        __syncthreads();

#pragma unroll
        for (int k = 0; k < 32; k++) {
            float a[4], b[8];
#pragma unroll
            for (int r = 0; r < 4; r++) a[r] = sA[ty * 4 + r][k];
#pragma unroll
            for (int c = 0; c < 8; c++) b[c] = sW[k][tx + 16 * c];
#pragma unroll
            for (int r = 0; r < 4; r++)
#pragma unroll
                for (int c = 0; c < 8; c++) acc[r][c] = fmaf(a[r], b[c], acc[r][c]);
        }
        __syncthreads();
    }

#pragma unroll
    for (int r = 0; r < 4; r++) {
        int row = rowBase + ty * 4 + r;
#pragma unroll
        for (int c = 0; c < 8; c++) {
            int col = tx + 16 * c;
            float val = acc[r][c] + bias[col];
            if (HEADMAJOR) {
                int b  = row >> 12;
                int l  = row & (L - 1);
                int h  = col >> 4;
                int d  = col & 15;
                size_t o = ((size_t)(b * H + h) * L + l) * DH + d;
                C[o] = val;
                if (Chi) {
                    __half hi = __float2half_rn(val);
                    Chi[o] = hi;
                    Clo[o] = __float2half_rn(val - __half2float(hi));
                }
            } else {
                C[(size_t)row * DM + col] = val;
            }
        }
    }
}

__global__ void __launch_bounds__(256)
qkv_gemm_kernel(const float* __restrict__ x,
                const float* __restrict__ Wq, const float* __restrict__ bq,
                const float* __restrict__ Wk, const float* __restrict__ bk,
                const float* __restrict__ Wv, const float* __restrict__ bv) {
    int which = blockIdx.y;
    const float* W    = (which == 0) ? Wq : (which == 1) ? Wk : Wv;
    const float* bias = (which == 0) ? bq : (which == 1) ? bk : bv;
    float* out        = (which == 0) ? g_Q : (which == 1) ? g_K : g_V;
    __half* ohi       = (which == 0) ? g_Qh : (which == 1) ? g_Kh : (__half*)0;
    __half* olo       = (which == 0) ? g_Ql : (which == 1) ? g_Kl : (__half*)0;
    gemm_body<true>(x, W, bias, out, ohi, olo);
}

__global__ void __launch_bounds__(256)
out_gemm_kernel(const float* __restrict__ Wo, const float* __restrict__ bo,
                float* __restrict__ out) {
    gemm_body<false>(g_ctx, Wo, bo, out, (__half*)0, (__half*)0);
}

// ---------------------------------------------------------------------------
// Pass A (split MMA, chained acc, double-buffered, 128-thread blocks):
// g_ml[q] = max_k(q.k) * C1.  Block = 4 warps x 16 queries = 64 queries.
// ---------------------------------------------------------------------------
__global__ void __launch_bounds__(128) rowmax_mma_kernel() {
    __shared__ __align__(16) __half sKh[2][CHK * 24];
    __shared__ __align__(16) __half sKl[2][CHK * 24];

    const int bh = blockIdx.y, tid = threadIdx.x;
    const int warp = tid >> 5, lane = tid & 31;
    const int g = lane >> 2, tg = lane & 3;
    const __half* Qhp = g_Qh + (size_t)bh * L * DH;
    const __half* Qlp = g_Ql + (size_t)bh * L * DH;
    const __half* Khp = g_Kh + (size_t)bh * L * DH;
    const __half* Klp = g_Kl + (size_t)bh * L * DH;

    const int q0 = blockIdx.x * 64 + warp * 16 + g;

    uint32_t ah[4], al[4];
    ah[0] = *(const uint32_t*)(Qhp + (size_t)q0 * 16 + tg * 2);
    ah[1] = *(const uint32_t*)(Qhp + (size_t)(q0 + 8) * 16 + tg * 2);
    ah[2] = *(const uint32_t*)(Qhp + (size_t)q0 * 16 + tg * 2 + 8);
    ah[3] = *(const uint32_t*)(Qhp + (size_t)(q0 + 8) * 16 + tg * 2 + 8);
    al[0] = *(const uint32_t*)(Qlp + (size_t)q0 * 16 + tg * 2);
    al[1] = *(const uint32_t*)(Qlp + (size_t)(q0 + 8) * 16 + tg * 2);
    al[2] = *(const uint32_t*)(Qlp + (size_t)q0 * 16 + tg * 2 + 8);
    al[3] = *(const uint32_t*)(Qlp + (size_t)(q0 + 8) * 16 + tg * 2 + 8);

    float mx0 = -1e30f, mx1 = -1e30f;

    const int lrow = (lane & 7) + ((lane >> 4) << 3);
    const int lcol = (lane & 8);

    auto load_chunk = [&](int buf, int ch) {
#pragma unroll
        for (int i = tid; i < 256; i += 128) {
            int row = i >> 1, h8 = (i & 1) * 8;
            cpasync16(smem_u32(&sKh[buf][row * 24 + h8]),
                      Khp + (size_t)(ch * CHK + row) * 16 + h8);
            cpasync16(smem_u32(&sKl[buf][row * 24 + h8]),
                      Klp + (size_t)(ch * CHK + row) * 16 + h8);
        }
    };

    load_chunk(0, 0);
    cp_commit();

    for (int ch = 0; ch < NCH; ch++) {
        int buf = ch & 1;
        if (ch + 1 < NCH) { load_chunk(buf ^ 1, ch + 1); cp_commit(); cp_wait<1>(); }
        else              { cp_wait<0>(); }
        __syncthreads();

        uint32_t baseh = smem_u32(&sKh[buf][lrow * 24 + lcol]);
        uint32_t basel = smem_u32(&sKl[buf][lrow * 24 + lcol]);
#pragma unroll
        for (int kb = 0; kb < CHK; kb += 16) {
            uint32_t rh[4], rl[4];
            ldsm4(rh, baseh + kb * 48);
            ldsm4(rl, basel + kb * 48);

            float c0[4], c1[4];
            mma_z(c0, ah, rh[0], rh[1]);
            mma_acc(c0, ah, rl[0], rl[1]);
            mma_acc(c0, al, rh[0], rh[1]);
            mma_z(c1, ah, rh[2], rh[3]);
            mma_acc(c1, ah, rl[2], rl[3]);
            mma_acc(c1, al, rh[2], rh[3]);

            mx0 = fmaxf(mx0, fmaxf(fmaxf(c0[0], c0[1]), fmaxf(c1[0], c1[1])));
            mx1 = fmaxf(mx1, fmaxf(fmaxf(c0[2], c0[3]), fmaxf(c1[2], c1[3])));
        }
        __syncthreads();
    }

    mx0 = fmaxf(mx0, __shfl_xor_sync(0xffffffffu, mx0, 1));
    mx0 = fmaxf(mx0, __shfl_xor_sync(0xffffffffu, mx0, 2));
    mx1 = fmaxf(mx1, __shfl_xor_sync(0xffffffffu, mx1, 1));
    mx1 = fmaxf(mx1, __shfl_xor_sync(0xffffffffu, mx1, 2));
    if (tg == 0) {
        g_ml[bh * L + q0]     = mx0 * C1;
        g_ml[bh * L + q0 + 8] = mx1 * C1;
    }
}

// ---------------------------------------------------------------------------
// Pass B (split MMA, chained acc, 128-thread blocks): warp owns 16 keys.
// Block = 4 warps x 16 keys = 64 keys; loops all queries.
// ---------------------------------------------------------------------------
__global__ void __launch_bounds__(128) keysum_mma_kernel() {
    __shared__ __align__(16) __half sQh[2][CHK * 24];
    __shared__ __align__(16) __half sQl[2][CHK * 24];
    __shared__ __align__(16) float  sM[2][CHK];

    const int bh = blockIdx.y, tid = threadIdx.x;
    const int warp = tid >> 5, lane = tid & 31;
    const int g = lane >> 2, tg = lane & 3;
    const __half* Qhp = g_Qh + (size_t)bh * L * DH;
    const __half* Qlp = g_Ql + (size_t)bh * L * DH;
    const __half* Khp = g_Kh + (size_t)bh * L * DH;
    const __half* Klp = g_Kl + (size_t)bh * L * DH;
    const float*  Mlp = g_ml + (size_t)bh * L;

    const int kbase = blockIdx.x * 64 + warp * 16;

    uint32_t kh0a = *(const uint32_t*)(Khp + (size_t)(kbase + g) * 16 + tg * 2);
    uint32_t kh1a = *(const uint32_t*)(Khp + (size_t)(kbase + g) * 16 + tg * 2 + 8);
    uint32_t kl0a = *(const uint32_t*)(Klp + (size_t)(kbase + g) * 16 + tg * 2);
    uint32_t kl1a = *(const uint32_t*)(Klp + (size_t)(kbase + g) * 16 + tg * 2 + 8);
    uint32_t kh0b = *(const uint32_t*)(Khp + (size_t)(kbase + 8 + g) * 16 + tg * 2);
    uint32_t kh1b = *(const uint32_t*)(Khp + (size_t)(kbase + 8 + g) * 16 + tg * 2 + 8);
    uint32_t kl0b = *(const uint32_t*)(Klp + (size_t)(kbase + 8 + g) * 16 + tg * 2);
    uint32_t kl1b = *(const uint32_t*)(Klp + (size_t)(kbase + 8 + g) * 16 + tg * 2 + 8);

    float acc_a0 = 0.0f, acc_a1 = 0.0f, acc_b0 = 0.0f, acc_b1 = 0.0f;

    const int mi = lane >> 3;
    const int lrow = (lane & 7) + ((mi & 1) << 3);
    const int lcol = (mi >> 1) << 3;

    auto load_chunk = [&](int buf, int ch) {
#pragma unroll
        for (int i = tid; i < 256; i += 128) {
            int row = i >> 1, h8 = (i & 1) * 8;
            cpasync16(smem_u32(&sQh[buf][row * 24 + h8]),
                      Qhp + (size_t)(ch * CHK + row) * 16 + h8);
            cpasync16(smem_u32(&sQl[buf][row * 24 + h8]),
                      Qlp + (size_t)(ch * CHK + row) * 16 + h8);
        }
        if (tid < CHK / 4)
            cpasync16(smem_u32(&sM[buf][tid * 4]), Mlp + ch * CHK + tid * 4);
    };

    load_chunk(0, 0);
    cp_commit();

    for (int ch = 0; ch < NCH; ch++) {
        int buf = ch & 1;
        if (ch + 1 < NCH) { load_chunk(buf ^ 1, ch + 1); cp_commit(); cp_wait<1>(); }
        else              { cp_wait<0>(); }
        __syncthreads();

        uint32_t baseh = smem_u32(&sQh[buf][lrow * 24 + lcol]);
        uint32_t basel = smem_u32(&sQl[buf][lrow * 24 + lcol]);
#pragma unroll
        for (int qb = 0; qb < CHK; qb += 16) {
            uint32_t qah[4], qal[4];
            ldsm4(qah, baseh + qb * 48);
            ldsm4(qal, basel + qb * 48);
            float ml0 = sM[buf][qb + g], ml1 = sM[buf][qb + g + 8];

            float ca[4], cb[4];
            mma_z(ca, qah, kh0a, kh1a);
            mma_acc(ca, qah, kl0a, kl1a);
            mma_acc(ca, qal, kh0a, kh1a);
            mma_z(cb, qah, kh0b, kh1b);
            mma_acc(cb, qah, kl0b, kl1b);
            mma_acc(cb, qal, kh0b, kh1b);

            acc_a0 += ex2f(fmaf(ca[0], C1, -ml0)) + ex2f(fmaf(ca[2], C1, -ml1));
            acc_a1 += ex2f(fmaf(ca[1], C1, -ml0)) + ex2f(fmaf(ca[3], C1, -ml1));
            acc_b0 += ex2f(fmaf(cb[0], C1, -ml0)) + ex2f(fmaf(cb[2], C1, -ml1));
            acc_b1 += ex2f(fmaf(cb[1], C1, -ml0)) + ex2f(fmaf(cb[3], C1, -ml1));
        }
        __syncthreads();
    }

#pragma unroll
    for (int s = 4; s <= 16; s <<= 1) {
        acc_a0 += __shfl_xor_sync(0xffffffffu, acc_a0, s);
        acc_a1 += __shfl_xor_sync(0xffffffffu, acc_a1, s);
        acc_b0 += __shfl_xor_sync(0xffffffffu, acc_b0, s);
        acc_b1 += __shfl_xor_sync(0xffffffffu, acc_b1, s);
    }
    if (g == 0) {
        g_mean[bh * L + kbase + tg * 2]         = acc_a0;
        g_mean[bh * L + kbase + tg * 2 + 1]     = acc_a1;
        g_mean[bh * L + kbase + 8 + tg * 2]     = acc_b0;
        g_mean[bh * L + kbase + 8 + tg * 2 + 1] = acc_b1;
    }
}

// ---------------------------------------------------------------------------
// Top-41 per (b,h): radix select with warp-shuffle suffix scan.
// ---------------------------------------------------------------------------
__global__ void __launch_bounds__(256) topk_kernel() {
    __shared__ int hist[256];
    __shared__ int sfx[256];
    __shared__ int wsum[8];
    __shared__ uint32_t s_prefix;
    __shared__ int s_need;
    __shared__ int s_cnt, s_eqc;
    __shared__ int eq_idx[64];

    const int bh = blockIdx.x, tid = threadIdx.x;
    const int lane = tid & 31, w = tid >> 5;

    uint32_t u[16];
#pragma unroll
    for (int j = 0; j < 16; j++) {
        uint32_t b = __float_as_uint(g_mean[bh * L + (j << 8) + tid]);
        u[j] = (b & 0x80000000u) ? ~b : (b | 0x80000000u);
    }

    uint32_t prefix = 0;
    int need = SK;
#pragma unroll
    for (int pass = 0; pass < 4; pass++) {
        int sh = 24 - pass * 8;
        hist[tid] = 0;
        __syncthreads();
#pragma unroll
        for (int j = 0; j < 16; j++) {
            bool act = (pass == 0) || ((u[j] >> (sh + 8)) == prefix);
            if (act) atomicAdd(&hist[(u[j] >> sh) & 255], 1);
        }
        __syncthreads();

        // warp-level suffix scan over 256 bins
        int v = hist[tid];
#pragma unroll
        for (int off = 1; off < 32; off <<= 1) {
            int t = __shfl_down_sync(0xffffffffu, v, off);
            if (lane + off < 32) v += t;
        }
        if (lane == 0) wsum[w] = v;
        __syncthreads();
        int add = 0;
#pragma unroll
        for (int ww = 0; ww < 8; ww++)
            if (ww > w) add += wsum[ww];
        v += add;
        sfx[tid] = v;
        __syncthreads();

        int nxt = (tid < 255) ? sfx[tid + 1] : 0;
        if (sfx[tid] >= need && nxt < need) {
            s_prefix = (prefix << 8) | (uint32_t)tid;
            s_need = need - nxt;
        }
        __syncthreads();
        prefix = s_prefix;
        need = s_need;
        __syncthreads();
    }

    const uint32_t T = prefix;
    if (tid == 0) { s_cnt = 0; s_eqc = 0; }
    __syncthreads();
#pragma unroll
    for (int j = 0; j < 16; j++) {
        if (u[j] > T) {
            int p = atomicAdd(&s_cnt, 1);
            g_idx[bh * SK + p] = (j << 8) + tid;
        } else if (u[j] == T) {
            int p = atomicAdd(&s_eqc, 1);
            if (p < 64) eq_idx[p] = (j << 8) + tid;
        }
    }
    __syncthreads();
    if (tid == 0) {
        int base = s_cnt;
        int m = s_eqc < 64 ? s_eqc : 64;
        for (int i = 1; i < m; i++) {
            int key = eq_idx[i], k2 = i - 1;
            while (k2 >= 0 && eq_idx[k2] > key) { eq_idx[k2 + 1] = eq_idx[k2]; k2--; }
            eq_idx[k2 + 1] = key;
        }
        for (int r = 0; r < need && r < m; r++)
            g_idx[bh * SK + base + r] = eq_idx[r];
    }
}

// ---------------------------------------------------------------------------
// Sparse attention: softmax(Q . Ks^T * 0.25) @ Vs, 41 sampled keys (exact fp32)
// ---------------------------------------------------------------------------
__global__ void __launch_bounds__(256) sparse_attn_kernel() {
    __shared__ float sKs[SK * DH];
    __shared__ float sVs[SK * DH];

    const int bh = blockIdx.y, tid = threadIdx.x;
    const float* Qb = g_Q + (size_t)bh * L * DH;
    const float* Kb = g_K + (size_t)bh * L * DH;
    const float* Vb = g_V + (size_t)bh * L * DH;

    for (int i = tid; i < SK * DH; i += 256) {
        int s = i >> 4, d = i & 15;
        int kk = g_idx[bh * SK + s];
        sKs[i] = Kb[(size_t)kk * DH + d];
        sVs[i] = Vb[(size_t)kk * DH + d];
    }
    __syncthreads();

    const int q = blockIdx.x * 256 + tid;
    const float4* qp = (const float4*)(Qb + (size_t)q * DH);
    float4 a0 = qp[0], a1 = qp[1], a2 = qp[2], a3 = qp[3];

    float sc[SK];
    float mx = -1e30f;
#pragma unroll
    for (int s = 0; s < SK; s++) {
        const float4* kp = (const float4*)(sKs + s * DH);
        float d = dot16(a0, a1, a2, a3, kp[0], kp[1], kp[2], kp[3]);
        sc[s] = d;
        mx = fmaxf(mx, d);
    }

    float sum = 0.0f;
    float4 o0 = {0, 0, 0, 0}, o1 = {0, 0, 0, 0}, o2 = {0, 0, 0, 0}, o3 = {0, 0, 0, 0};
#pragma unroll
    for (int s = 0; s < SK; s++) {
        float w = ex2f((sc[s] - mx) * C1);
        sum += w;
        const float4* vp = (const float4*)(sVs + s * DH);
        float4 v0 = vp[0], v1 = vp[1], v2 = vp[2], v3 = vp[3];
        o0.x = fmaf(w, v0.x, o0.x); o0.y = fmaf(w, v0.y, o0.y);
        o0.z = fmaf(w, v0.z, o0.z); o0.w = fmaf(w, v0.w, o0.w);
        o1.x = fmaf(w, v1.x, o1.x); o1.y = fmaf(w, v1.y, o1.y);
        o1.z = fmaf(w, v1.z, o1.z); o1.w = fmaf(w, v1.w, o1.w);
        o2.x = fmaf(w, v2.x, o2.x); o2.y = fmaf(w, v2.y, o2.y);
        o2.z = fmaf(w, v2.z, o2.z); o2.w = fmaf(w, v2.w, o2.w);
        o3.x = fmaf(w, v3.x, o3.x); o3.y = fmaf(w, v3.y, o3.y);
        o3.z = fmaf(w, v3.z, o3.z); o3.w = fmaf(w, v3.w, o3.w);
    }
    float inv = 1.0f / sum;

    const int b = bh >> 3;
    const int h = bh & 7;
    float* op = g_ctx + ((size_t)b * L + q) * DM + h * DH;
    *(float4*)(op + 0)  = make_float4(o0.x * inv, o0.y * inv, o0.z * inv, o0.w * inv);
    *(float4*)(op + 4)  = make_float4(o1.x * inv, o1.y * inv, o1.z * inv, o1.w * inv);
    *(float4*)(op + 8)  = make_float4(o2.x * inv, o2.y * inv, o2.z * inv, o2.w * inv);
    *(float4*)(op + 12) = make_float4(o3.x * inv, o3.y * inv, o3.z * inv, o3.w * inv);
}

// ---------------------------------------------------------------------------
extern "C" void kernel_launch(void* const* d_in, const int* in_sizes, int n_in,
                              void* d_out, int out_size) {
    const float* x  = (const float*)d_in[0];
    const float* Wq = (const float*)d_in[1];
    const float* bq = (const float*)d_in[2];
    const float* Wk = (const float*)d_in[3];
    const float* bk = (const float*)d_in[4];
    const float* Wv = (const float*)d_in[5];
    const float* bv = (const float*)d_in[6];
    const float* Wo = (const float*)d_in[7];
    const float* bo = (const float*)d_in[8];

    qkv_gemm_kernel<<<dim3(128, 3), 256>>>(x, Wq, bq, Wk, bk, Wv, bv);
    rowmax_mma_kernel<<<dim3(64, NBH), 128>>>();
    keysum_mma_kernel<<<dim3(64, NBH), 128>>>();
    topk_kernel<<<NBH, 256>>>();
    sparse_attn_kernel<<<dim3(16, NBH), 256>>>();
    out_gemm_kernel<<<128, 256>>>(Wo, bo, (float*)d_out);
}

// round 16
// speedup vs baseline: 1.1133x; 1.0094x over previous
#include <cuda_runtime.h>
#include <cuda_fp16.h>
#include <cstdint>

// ---------------------------------------------------------------------------
// ProbSparseAttention  B=2, L=4096, dm=128, H=8, D=16, sample_k=41
// Score passes: split-fp16 (hi+lo) mma.sync, chained accumulator, cp.async
// double-buffered, 128-thread blocks, ldsm software pipelining.
// Top-k: radix select. GEMMs + output path exact fp32.
// ---------------------------------------------------------------------------

#define L      4096
#define DM     128
#define H      8
#define DH     16
#define NBH    16
#define SK     41
#define LOG2E  1.4426950408889634f
#define C1     (0.25f * LOG2E)
#define CHK    128
#define NCH    (L / CHK)

// Scratch (device globals; no allocation allowed)
__device__ float  g_Q[NBH * L * DH];
__device__ float  g_K[NBH * L * DH];
__device__ float  g_V[NBH * L * DH];
__device__ __half g_Qh[NBH * L * DH];
__device__ __half g_Ql[NBH * L * DH];
__device__ __half g_Kh[NBH * L * DH];
__device__ __half g_Kl[NBH * L * DH];
__device__ float  g_ml[NBH * L];
__device__ float  g_mean[NBH * L];
__device__ int    g_idx[NBH * SK];
__device__ float  g_ctx[2 * L * DM];

__device__ __forceinline__ float ex2f(float x) {
    float r;
    asm("ex2.approx.ftz.f32 %0, %1;" : "=f"(r) : "f"(x));
    return r;
}
__device__ __forceinline__ uint32_t smem_u32(const void* p) {
    return (uint32_t)__cvta_generic_to_shared(p);
}
__device__ __forceinline__ void cpasync16(uint32_t saddr, const void* gptr) {
    asm volatile("cp.async.ca.shared.global [%0], [%1], 16;" :: "r"(saddr), "l"(gptr));
}
__device__ __forceinline__ void cp_commit() { asm volatile("cp.async.commit_group;"); }
template <int N>
__device__ __forceinline__ void cp_wait() { asm volatile("cp.async.wait_group %0;" :: "n"(N)); }

__device__ __forceinline__ void ldsm4(uint32_t r[4], uint32_t addr) {
    asm volatile("ldmatrix.sync.aligned.m8n8.x4.shared.b16 {%0,%1,%2,%3}, [%4];"
                 : "=r"(r[0]), "=r"(r[1]), "=r"(r[2]), "=r"(r[3]) : "r"(addr));
}
__device__ __forceinline__ void mma_z(float c[4], const uint32_t a[4],
                                      uint32_t b0, uint32_t b1) {
    asm volatile(
        "mma.sync.aligned.m16n8k16.row.col.f32.f16.f16.f32 "
        "{%0,%1,%2,%3}, {%4,%5,%6,%7}, {%8,%9}, {%10,%11,%12,%13};"
        : "=f"(c[0]), "=f"(c[1]), "=f"(c[2]), "=f"(c[3])
        : "r"(a[0]), "r"(a[1]), "r"(a[2]), "r"(a[3]), "r"(b0), "r"(b1),
          "f"(0.0f), "f"(0.0f), "f"(0.0f), "f"(0.0f));
}
__device__ __forceinline__ void mma_acc(float c[4], const uint32_t a[4],
                                        uint32_t b0, uint32_t b1) {
    asm volatile(
        "mma.sync.aligned.m16n8k16.row.col.f32.f16.f16.f32 "
        "{%0,%1,%2,%3}, {%4,%5,%6,%7}, {%8,%9}, {%0,%1,%2,%3};"
        : "+f"(c[0]), "+f"(c[1]), "+f"(c[2]), "+f"(c[3])
        : "r"(a[0]), "r"(a[1]), "r"(a[2]), "r"(a[3]), "r"(b0), "r"(b1));
}

__device__ __forceinline__ float dot16(const float4 a0, const float4 a1,
                                       const float4 a2, const float4 a3,
                                       const float4 b0, const float4 b1,
                                       const float4 b2, const float4 b3) {
    float s0 = a0.x * b0.x; s0 = fmaf(a0.y, b0.y, s0); s0 = fmaf(a0.z, b0.z, s0); s0 = fmaf(a0.w, b0.w, s0);
    float s1 = a1.x * b1.x; s1 = fmaf(a1.y, b1.y, s1); s1 = fmaf(a1.z, b1.z, s1); s1 = fmaf(a1.w, b1.w, s1);
    float s2 = a2.x * b2.x; s2 = fmaf(a2.y, b2.y, s2); s2 = fmaf(a2.z, b2.z, s2); s2 = fmaf(a2.w, b2.w, s2);
    float s3 = a3.x * b3.x; s3 = fmaf(a3.y, b3.y, s3); s3 = fmaf(a3.z, b3.z, s3); s3 = fmaf(a3.w, b3.w, s3);
    return (s0 + s1) + (s2 + s3);
}

// ---------------------------------------------------------------------------
// GEMM: C[8192,128] = A[8192,128] @ W[128,128] + bias (fp32, smem-tiled).
// HEADMAJOR also emits split-fp16 (hi, lo) copies for the score passes.
// ---------------------------------------------------------------------------
template <bool HEADMAJOR>
__device__ __forceinline__ void gemm_body(const float* __restrict__ A,
                                          const float* __restrict__ W,
                                          const float* __restrict__ bias,
                                          float* __restrict__ C,
                                          __half* __restrict__ Chi,
                                          __half* __restrict__ Clo) {
    __shared__ float sA[64][33];
    __shared__ float sW[32][128];

    const int tid = threadIdx.x;
    const int tx = tid & 15;
    const int ty = tid >> 4;
    const int rowBase = blockIdx.x * 64;

    float acc[4][8];
#pragma unroll
    for (int r = 0; r < 4; r++)
#pragma unroll
        for (int c = 0; c < 8; c++) acc[r][c] = 0.0f;

    for (int kc = 0; kc < 128; kc += 32) {
#pragma unroll
        for (int i = tid; i < 512; i += 256) {
            int r  = i >> 3;
            int c4 = i & 7;
            float4 v = *(const float4*)(A + (size_t)(rowBase + r) * DM + kc + c4 * 4);
            sA[r][c4 * 4 + 0] = v.x;
            sA[r][c4 * 4 + 1] = v.y;
            sA[r][c4 * 4 + 2] = v.z;
            sA[r][c4 * 4 + 3] = v.w;
        }
#pragma unroll
        for (int i = tid; i < 1024; i += 256) {
            int r  = i >> 5;
            int c4 = i & 31;
            *(float4*)(&sW[r][c4 * 4]) = *(const float4*)(W + (size_t)(kc + r) * DM + c4 * 4);
        }
        __syncthreads();

#pragma unroll
        for (int k = 0; k < 32; k++) {
            float a[4], b[8];
#pragma unroll
            for (int r = 0; r < 4; r++) a[r] = sA[ty * 4 + r][k];
#pragma unroll
            for (int c = 0; c < 8; c++) b[c] = sW[k][tx + 16 * c];
#pragma unroll
            for (int r = 0; r < 4; r++)
#pragma unroll
                for (int c = 0; c < 8; c++) acc[r][c] = fmaf(a[r], b[c], acc[r][c]);
        }
        __syncthreads();
    }

#pragma unroll
    for (int r = 0; r < 4; r++) {
        int row = rowBase + ty * 4 + r;
#pragma unroll
        for (int c = 0; c < 8; c++) {
            int col = tx + 16 * c;
            float val = acc[r][c] + bias[col];
            if (HEADMAJOR) {
                int b  = row >> 12;
                int l  = row & (L - 1);
                int h  = col >> 4;
                int d  = col & 15;
                size_t o = ((size_t)(b * H + h) * L + l) * DH + d;
                C[o] = val;
                if (Chi) {
                    __half hi = __float2half_rn(val);
                    Chi[o] = hi;
                    Clo[o] = __float2half_rn(val - __half2float(hi));
                }
            } else {
                C[(size_t)row * DM + col] = val;
            }
        }
    }
}

__global__ void __launch_bounds__(256)
qkv_gemm_kernel(const float* __restrict__ x,
                const float* __restrict__ Wq, const float* __restrict__ bq,
                const float* __restrict__ Wk, const float* __restrict__ bk,
                const float* __restrict__ Wv, const float* __restrict__ bv) {
    int which = blockIdx.y;
    const float* W    = (which == 0) ? Wq : (which == 1) ? Wk : Wv;
    const float* bias = (which == 0) ? bq : (which == 1) ? bk : bv;
    float* out        = (which == 0) ? g_Q : (which == 1) ? g_K : g_V;
    __half* ohi       = (which == 0) ? g_Qh : (which == 1) ? g_Kh : (__half*)0;
    __half* olo       = (which == 0) ? g_Ql : (which == 1) ? g_Kl : (__half*)0;
    gemm_body<true>(x, W, bias, out, ohi, olo);
}

__global__ void __launch_bounds__(256)
out_gemm_kernel(const float* __restrict__ Wo, const float* __restrict__ bo,
                float* __restrict__ out) {
    gemm_body<false>(g_ctx, Wo, bo, out, (__half*)0, (__half*)0);
}

// ---------------------------------------------------------------------------
// Pass A (split MMA, chained acc, double-buffered, 128-thread blocks,
// ldsm prefetch, 4 independent max accumulators):
// g_ml[q] = max_k(q.k) * C1.  Block = 4 warps x 16 queries = 64 queries.
// ---------------------------------------------------------------------------
__global__ void __launch_bounds__(128) rowmax_mma_kernel() {
    __shared__ __align__(16) __half sKh[2][CHK * 24];
    __shared__ __align__(16) __half sKl[2][CHK * 24];

    const int bh = blockIdx.y, tid = threadIdx.x;
    const int warp = tid >> 5, lane = tid & 31;
    const int g = lane >> 2, tg = lane & 3;
    const __half* Qhp = g_Qh + (size_t)bh * L * DH;
    const __half* Qlp = g_Ql + (size_t)bh * L * DH;
    const __half* Khp = g_Kh + (size_t)bh * L * DH;
    const __half* Klp = g_Kl + (size_t)bh * L * DH;

    const int q0 = blockIdx.x * 64 + warp * 16 + g;

    uint32_t ah[4], al[4];
    ah[0] = *(const uint32_t*)(Qhp + (size_t)q0 * 16 + tg * 2);
    ah[1] = *(const uint32_t*)(Qhp + (size_t)(q0 + 8) * 16 + tg * 2);
    ah[2] = *(const uint32_t*)(Qhp + (size_t)q0 * 16 + tg * 2 + 8);
    ah[3] = *(const uint32_t*)(Qhp + (size_t)(q0 + 8) * 16 + tg * 2 + 8);
    al[0] = *(const uint32_t*)(Qlp + (size_t)q0 * 16 + tg * 2);
    al[1] = *(const uint32_t*)(Qlp + (size_t)(q0 + 8) * 16 + tg * 2);
    al[2] = *(const uint32_t*)(Qlp + (size_t)q0 * 16 + tg * 2 + 8);
    al[3] = *(const uint32_t*)(Qlp + (size_t)(q0 + 8) * 16 + tg * 2 + 8);

    // 4 independent max accumulators (exact: max is associative)
    float mxA = -1e30f, mxB = -1e30f, mxC = -1e30f, mxD = -1e30f;

    const int lrow = (lane & 7) + ((lane >> 4) << 3);
    const int lcol = (lane & 8);

    auto load_chunk = [&](int buf, int ch) {
#pragma unroll
        for (int i = tid; i < 256; i += 128) {
            int row = i >> 1, h8 = (i & 1) * 8;
            cpasync16(smem_u32(&sKh[buf][row * 24 + h8]),
                      Khp + (size_t)(ch * CHK + row) * 16 + h8);
            cpasync16(smem_u32(&sKl[buf][row * 24 + h8]),
                      Klp + (size_t)(ch * CHK + row) * 16 + h8);
        }
    };

    load_chunk(0, 0);
    cp_commit();

    for (int ch = 0; ch < NCH; ch++) {
        int buf = ch & 1;
        if (ch + 1 < NCH) { load_chunk(buf ^ 1, ch + 1); cp_commit(); cp_wait<1>(); }
        else              { cp_wait<0>(); }
        __syncthreads();

        uint32_t baseh = smem_u32(&sKh[buf][lrow * 24 + lcol]);
        uint32_t basel = smem_u32(&sKl[buf][lrow * 24 + lcol]);

        uint32_t rh[4], rl[4];
        ldsm4(rh, baseh);
        ldsm4(rl, basel);
#pragma unroll
        for (int kb = 0; kb < CHK; kb += 16) {
            uint32_t curh[4], curl[4];
#pragma unroll
            for (int i = 0; i < 4; i++) { curh[i] = rh[i]; curl[i] = rl[i]; }
            if (kb + 16 < CHK) {                 // prefetch next tile
                ldsm4(rh, baseh + (kb + 16) * 48);
                ldsm4(rl, basel + (kb + 16) * 48);
            }

            float c0[4], c1[4];
            mma_z(c0, ah, curh[0], curh[1]);
            mma_acc(c0, ah, curl[0], curl[1]);
            mma_acc(c0, al, curh[0], curh[1]);
            mma_z(c1, ah, curh[2], curh[3]);
            mma_acc(c1, ah, curl[2], curl[3]);
            mma_acc(c1, al, curh[2], curh[3]);

            mxA = fmaxf(mxA, c0[0]); mxA = fmaxf(mxA, c1[0]);
            mxB = fmaxf(mxB, c0[1]); mxB = fmaxf(mxB, c1[1]);
            mxC = fmaxf(mxC, c0[2]); mxC = fmaxf(mxC, c1[2]);
            mxD = fmaxf(mxD, c0[3]); mxD = fmaxf(mxD, c1[3]);
        }
        __syncthreads();
    }

    float mx0 = fmaxf(mxA, mxB);
    float mx1 = fmaxf(mxC, mxD);
    mx0 = fmaxf(mx0, __shfl_xor_sync(0xffffffffu, mx0, 1));
    mx0 = fmaxf(mx0, __shfl_xor_sync(0xffffffffu, mx0, 2));
    mx1 = fmaxf(mx1, __shfl_xor_sync(0xffffffffu, mx1, 1));
    mx1 = fmaxf(mx1, __shfl_xor_sync(0xffffffffu, mx1, 2));
    if (tg == 0) {
        g_ml[bh * L + q0]     = mx0 * C1;
        g_ml[bh * L + q0 + 8] = mx1 * C1;
    }
}

// ---------------------------------------------------------------------------
// Pass B (split MMA, chained acc, 128-thread blocks, ldsm prefetch):
// warp owns 16 keys; block = 4 warps x 16 keys = 64 keys; loops all queries.
// ---------------------------------------------------------------------------
__global__ void __launch_bounds__(128) keysum_mma_kernel() {
    __shared__ __align__(16) __half sQh[2][CHK * 24];
    __shared__ __align__(16) __half sQl[2][CHK * 24];
    __shared__ __align__(16) float  sM[2][CHK];

    const int bh = blockIdx.y, tid = threadIdx.x;
    const int warp = tid >> 5, lane = tid & 31;
    const int g = lane >> 2, tg = lane & 3;
    const __half* Qhp = g_Qh + (size_t)bh * L * DH;
    const __half* Qlp = g_Ql + (size_t)bh * L * DH;
    const __half* Khp = g_Kh + (size_t)bh * L * DH;
    const __half* Klp = g_Kl + (size_t)bh * L * DH;
    const float*  Mlp = g_ml + (size_t)bh * L;

    const int kbase = blockIdx.x * 64 + warp * 16;

    uint32_t kh0a = *(const uint32_t*)(Khp + (size_t)(kbase + g) * 16 + tg * 2);
    uint32_t kh1a = *(const uint32_t*)(Khp + (size_t)(kbase + g) * 16 + tg * 2 + 8);
    uint32_t kl0a = *(const uint32_t*)(Klp + (size_t)(kbase + g) * 16 + tg * 2);
    uint32_t kl1a = *(const uint32_t*)(Klp + (size_t)(kbase + g) * 16 + tg * 2 + 8);
    uint32_t kh0b = *(const uint32_t*)(Khp + (size_t)(kbase + 8 + g) * 16 + tg * 2);
    uint32_t kh1b = *(const uint32_t*)(Khp + (size_t)(kbase + 8 + g) * 16 + tg * 2 + 8);
    uint32_t kl0b = *(const uint32_t*)(Klp + (size_t)(kbase + 8 + g) * 16 + tg * 2);
    uint32_t kl1b = *(const uint32_t*)(Klp + (size_t)(kbase + 8 + g) * 16 + tg * 2 + 8);

    float acc_a0 = 0.0f, acc_a1 = 0.0f, acc_b0 = 0.0f, acc_b1 = 0.0f;

    const int mi = lane >> 3;
    const int lrow = (lane & 7) + ((mi & 1) << 3);
    const int lcol = (mi >> 1) << 3;

    auto load_chunk = [&](int buf, int ch) {
#pragma unroll
        for (int i = tid; i < 256; i += 128) {
            int row = i >> 1, h8 = (i & 1) * 8;
            cpasync16(smem_u32(&sQh[buf][row * 24 + h8]),
                      Qhp + (size_t)(ch * CHK + row) * 16 + h8);
            cpasync16(smem_u32(&sQl[buf][row * 24 + h8]),
                      Qlp + (size_t)(ch * CHK + row) * 16 + h8);
        }
        if (tid < CHK / 4)
            cpasync16(smem_u32(&sM[buf][tid * 4]), Mlp + ch * CHK + tid * 4);
    };

    load_chunk(0, 0);
    cp_commit();

    for (int ch = 0; ch < NCH; ch++) {
        int buf = ch & 1;
        if (ch + 1 < NCH) { load_chunk(buf ^ 1, ch + 1); cp_commit(); cp_wait<1>(); }
        else              { cp_wait<0>(); }
        __syncthreads();

        uint32_t baseh = smem_u32(&sQh[buf][lrow * 24 + lcol]);
        uint32_t basel = smem_u32(&sQl[buf][lrow * 24 + lcol]);

        uint32_t qh[4], ql[4];
        ldsm4(qh, baseh);
        ldsm4(ql, basel);
#pragma unroll
        for (int qb = 0; qb < CHK; qb += 16) {
            uint32_t curh[4], curl[4];
#pragma unroll
            for (int i = 0; i < 4; i++) { curh[i] = qh[i]; curl[i] = ql[i]; }
            if (qb + 16 < CHK) {                 // prefetch next tile
                ldsm4(qh, baseh + (qb + 16) * 48);
                ldsm4(ql, basel + (qb + 16) * 48);
            }

            float ml0 = sM[buf][qb + g], ml1 = sM[buf][qb + g + 8];

            float ca[4], cb[4];
            mma_z(ca, curh, kh0a, kh1a);
            mma_acc(ca, curh, kl0a, kl1a);
            mma_acc(ca, curl, kh0a, kh1a);
            mma_z(cb, curh, kh0b, kh1b);
            mma_acc(cb, curh, kl0b, kl1b);
            mma_acc(cb, curl, kh0b, kh1b);

            acc_a0 += ex2f(fmaf(ca[0], C1, -ml0)) + ex2f(fmaf(ca[2], C1, -ml1));
            acc_a1 += ex2f(fmaf(ca[1], C1, -ml0)) + ex2f(fmaf(ca[3], C1, -ml1));
            acc_b0 += ex2f(fmaf(cb[0], C1, -ml0)) + ex2f(fmaf(cb[2], C1, -ml1));
            acc_b1 += ex2f(fmaf(cb[1], C1, -ml0)) + ex2f(fmaf(cb[3], C1, -ml1));
        }
        __syncthreads();
    }

#pragma unroll
    for (int s = 4; s <= 16; s <<= 1) {
        acc_a0 += __shfl_xor_sync(0xffffffffu, acc_a0, s);
        acc_a1 += __shfl_xor_sync(0xffffffffu, acc_a1, s);
        acc_b0 += __shfl_xor_sync(0xffffffffu, acc_b0, s);
        acc_b1 += __shfl_xor_sync(0xffffffffu, acc_b1, s);
    }
    if (g == 0) {
        g_mean[bh * L + kbase + tg * 2]         = acc_a0;
        g_mean[bh * L + kbase + tg * 2 + 1]     = acc_a1;
        g_mean[bh * L + kbase + 8 + tg * 2]     = acc_b0;
        g_mean[bh * L + kbase + 8 + tg * 2 + 1] = acc_b1;
    }
}

// ---------------------------------------------------------------------------
// Top-41 per (b,h): radix select with warp-shuffle suffix scan.
// ---------------------------------------------------------------------------
__global__ void __launch_bounds__(256) topk_kernel() {
    __shared__ int hist[256];
    __shared__ int sfx[256];
    __shared__ int wsum[8];
    __shared__ uint32_t s_prefix;
    __shared__ int s_need;
    __shared__ int s_cnt, s_eqc;
    __shared__ int eq_idx[64];

    const int bh = blockIdx.x, tid = threadIdx.x;
    const int lane = tid & 31, w = tid >> 5;

    uint32_t u[16];
#pragma unroll
    for (int j = 0; j < 16; j++) {
        uint32_t b = __float_as_uint(g_mean[bh * L + (j << 8) + tid]);
        u[j] = (b & 0x80000000u) ? ~b : (b | 0x80000000u);
    }

    uint32_t prefix = 0;
    int need = SK;
#pragma unroll
    for (int pass = 0; pass < 4; pass++) {
        int sh = 24 - pass * 8;
        hist[tid] = 0;
        __syncthreads();
#pragma unroll
        for (int j = 0; j < 16; j++) {
            bool act = (pass == 0) || ((u[j] >> (sh + 8)) == prefix);
            if (act) atomicAdd(&hist[(u[j] >> sh) & 255], 1);
        }
        __syncthreads();

        int v = hist[tid];
#pragma unroll
        for (int off = 1; off < 32; off <<= 1) {
            int t = __shfl_down_sync(0xffffffffu, v, off);
            if (lane + off < 32) v += t;
        }
        if (lane == 0) wsum[w] = v;
        __syncthreads();
        int add = 0;
#pragma unroll
        for (int ww = 0; ww < 8; ww++)
            if (ww > w) add += wsum[ww];
        v += add;
        sfx[tid] = v;
        __syncthreads();

        int nxt = (tid < 255) ? sfx[tid + 1] : 0;
        if (sfx[tid] >= need && nxt < need) {
            s_prefix = (prefix << 8) | (uint32_t)tid;
            s_need = need - nxt;
        }
        __syncthreads();
        prefix = s_prefix;
        need = s_need;
        __syncthreads();
    }

    const uint32_t T = prefix;
    if (tid == 0) { s_cnt = 0; s_eqc = 0; }
    __syncthreads();
#pragma unroll
    for (int j = 0; j < 16; j++) {
        if (u[j] > T) {
            int p = atomicAdd(&s_cnt, 1);
            g_idx[bh * SK + p] = (j << 8) + tid;
        } else if (u[j] == T) {
            int p = atomicAdd(&s_eqc, 1);
            if (p < 64) eq_idx[p] = (j << 8) + tid;
        }
    }
    __syncthreads();
    if (tid == 0) {
        int base = s_cnt;
        int m = s_eqc < 64 ? s_eqc : 64;
        for (int i = 1; i < m; i++) {
            int key = eq_idx[i], k2 = i - 1;
            while (k2 >= 0 && eq_idx[k2] > key) { eq_idx[k2 + 1] = eq_idx[k2]; k2--; }
            eq_idx[k2 + 1] = key;
        }
        for (int r = 0; r < need && r < m; r++)
            g_idx[bh * SK + base + r] = eq_idx[r];
    }
}

// ---------------------------------------------------------------------------
// Sparse attention: softmax(Q . Ks^T * 0.25) @ Vs, 41 sampled keys (exact fp32)
// ---------------------------------------------------------------------------
__global__ void __launch_bounds__(256) sparse_attn_kernel() {
    __shared__ float sKs[SK * DH];
    __shared__ float sVs[SK * DH];

    const int bh = blockIdx.y, tid = threadIdx.x;
    const float* Qb = g_Q + (size_t)bh * L * DH;
    const float* Kb = g_K + (size_t)bh * L * DH;
    const float* Vb = g_V + (size_t)bh * L * DH;

    for (int i = tid; i < SK * DH; i += 256) {
        int s = i >> 4, d = i & 15;
        int kk = g_idx[bh * SK + s];
        sKs[i] = Kb[(size_t)kk * DH + d];
        sVs[i] = Vb[(size_t)kk * DH + d];
    }
    __syncthreads();

    const int q = blockIdx.x * 256 + tid;
    const float4* qp = (const float4*)(Qb + (size_t)q * DH);
    float4 a0 = qp[0], a1 = qp[1], a2 = qp[2], a3 = qp[3];

    float sc[SK];
    float mx = -1e30f;
#pragma unroll
    for (int s = 0; s < SK; s++) {
        const float4* kp = (const float4*)(sKs + s * DH);
        float d = dot16(a0, a1, a2, a3, kp[0], kp[1], kp[2], kp[3]);
        sc[s] = d;
        mx = fmaxf(mx, d);
    }

    float sum = 0.0f;
    float4 o0 = {0, 0, 0, 0}, o1 = {0, 0, 0, 0}, o2 = {0, 0, 0, 0}, o3 = {0, 0, 0, 0};
#pragma unroll
    for (int s = 0; s < SK; s++) {
        float w = ex2f((sc[s] - mx) * C1);
        sum += w;
        const float4* vp = (const float4*)(sVs + s * DH);
        float4 v0 = vp[0], v1 = vp[1], v2 = vp[2], v3 = vp[3];
        o0.x = fmaf(w, v0.x, o0.x); o0.y = fmaf(w, v0.y, o0.y);
        o0.z = fmaf(w, v0.z, o0.z); o0.w = fmaf(w, v0.w, o0.w);
        o1.x = fmaf(w, v1.x, o1.x); o1.y = fmaf(w, v1.y, o1.y);
        o1.z = fmaf(w, v1.z, o1.z); o1.w = fmaf(w, v1.w, o1.w);
        o2.x = fmaf(w, v2.x, o2.x); o2.y = fmaf(w, v2.y, o2.y);
        o2.z = fmaf(w, v2.z, o2.z); o2.w = fmaf(w, v2.w, o2.w);
        o3.x = fmaf(w, v3.x, o3.x); o3.y = fmaf(w, v3.y, o3.y);
        o3.z = fmaf(w, v3.z, o3.z); o3.w = fmaf(w, v3.w, o3.w);
    }
    float inv = 1.0f / sum;

    const int b = bh >> 3;
    const int h = bh & 7;
    float* op = g_ctx + ((size_t)b * L + q) * DM + h * DH;
    *(float4*)(op + 0)  = make_float4(o0.x * inv, o0.y * inv, o0.z * inv, o0.w * inv);
    *(float4*)(op + 4)  = make_float4(o1.x * inv, o1.y * inv, o1.z * inv, o1.w * inv);
    *(float4*)(op + 8)  = make_float4(o2.x * inv, o2.y * inv, o2.z * inv, o2.w * inv);
    *(float4*)(op + 12) = make_float4(o3.x * inv, o3.y * inv, o3.z * inv, o3.w * inv);
}

// ---------------------------------------------------------------------------
extern "C" void kernel_launch(void* const* d_in, const int* in_sizes, int n_in,
                              void* d_out, int out_size) {
    const float* x  = (const float*)d_in[0];
    const float* Wq = (const float*)d_in[1];
    const float* bq = (const float*)d_in[2];
    const float* Wk = (const float*)d_in[3];
    const float* bk = (const float*)d_in[4];
    const float* Wv = (const float*)d_in[5];
    const float* bv = (const float*)d_in[6];
    const float* Wo = (const float*)d_in[7];
    const float* bo = (const float*)d_in[8];

    qkv_gemm_kernel<<<dim3(128, 3), 256>>>(x, Wq, bq, Wk, bk, Wv, bv);
    rowmax_mma_kernel<<<dim3(64, NBH), 128>>>();
    keysum_mma_kernel<<<dim3(64, NBH), 128>>>();
    topk_kernel<<<NBH, 256>>>();
    sparse_attn_kernel<<<dim3(16, NBH), 256>>>();
    out_gemm_kernel<<<128, 256>>>(Wo, bo, (float*)d_out);
}